// round 1
// baseline (speedup 1.0000x reference)
#include <cuda_runtime.h>
#include <cuda_bf16.h>
#include <cstdint>

// Problem constants (fixed shapes: B=1, L=1024, C_Z=128, C_S=1024, C_S_OUT=1024)
#define LDIM 1024
#define CDIM 128
#define PADA 136            // bf16 elems per smem row (128 + 8 pad) -> 272B stride, ldmatrix conflict-free
#define NLB  64             // number of l-blocks
#define LBSZ 16             // l rows per CTA
#define SMEM_PAIR 142336

// ---------------- device scratch (static allocations are allowed) ----------------
__device__ float g_scratch_c[8ull  * 1024ull * 128ull];   // [m_block][l][c]   4 MB
__device__ float g_scratch_r[64ull * 1024ull * 128ull];   // [l_block][m][c]  32 MB
__device__ float g_catf[1024ull * 1280ull];               // concat rows (f32) 5 MB
__device__ float g_norm_c[1024];
__device__ float g_norm_r[1024];

// ---------------- MMA helpers ----------------
__device__ __forceinline__ void ldsm4(uint32_t &r0, uint32_t &r1, uint32_t &r2, uint32_t &r3, uint32_t addr) {
    asm volatile("ldmatrix.sync.aligned.m8n8.x4.shared.b16 {%0,%1,%2,%3}, [%4];"
                 : "=r"(r0), "=r"(r1), "=r"(r2), "=r"(r3) : "r"(addr));
}
__device__ __forceinline__ void mma_bf16(float* d, uint32_t a0, uint32_t a1, uint32_t a2, uint32_t a3,
                                         uint32_t b0, uint32_t b1) {
    asm volatile("mma.sync.aligned.m16n8k16.row.col.f32.bf16.bf16.f32 "
                 "{%0,%1,%2,%3}, {%4,%5,%6,%7}, {%8,%9}, {%0,%1,%2,%3};"
                 : "+f"(d[0]), "+f"(d[1]), "+f"(d[2]), "+f"(d[3])
                 : "r"(a0), "r"(a1), "r"(a2), "r"(a3), "r"(b0), "r"(b1));
}
__device__ __forceinline__ void mma_tf32(float* d, uint32_t a0, uint32_t a1, uint32_t a2, uint32_t a3,
                                         uint32_t b0, uint32_t b1) {
    asm volatile("mma.sync.aligned.m16n8k8.row.col.f32.tf32.tf32.f32 "
                 "{%0,%1,%2,%3}, {%4,%5,%6,%7}, {%8,%9}, {%0,%1,%2,%3};"
                 : "+f"(d[0]), "+f"(d[1]), "+f"(d[2]), "+f"(d[3])
                 : "r"(a0), "r"(a1), "r"(a2), "r"(a3), "r"(b0), "r"(b1));
}
__device__ __forceinline__ uint32_t f2tf(float f) {
    uint32_t r; asm("cvt.rna.tf32.f32 %0, %1;" : "=r"(r) : "f"(f)); return r;
}

// 128x128x128 bf16 GEMM tile: D(128m x 128n) += A(128x128,K-major) * B(128n x 128k,K-major)^T
// abase/bbase are per-lane ldmatrix base addresses (already include warp row offset + lane offsets).
__device__ __forceinline__ void gemm128(uint32_t abase, uint32_t bbase, float* d) {
#pragma unroll
    for (int k = 0; k < 8; k++) {
        uint32_t a0, a1, a2, a3;
        ldsm4(a0, a1, a2, a3, abase + k * 32);
#pragma unroll
        for (int ntp = 0; ntp < 8; ntp++) {
            uint32_t b0, b1, b2, b3;
            ldsm4(b0, b1, b2, b3, bbase + ntp * (16 * PADA * 2) + k * 32);
            mma_bf16(d + ntp * 8,     a0, a1, a2, a3, b0, b1);
            mma_bf16(d + ntp * 8 + 4, a0, a1, a2, a3, b2, b3);
        }
    }
}

// ---------------- K0: masked-norm vectors ----------------
__global__ void norm_kernel(const float* __restrict__ mask) {
    int t = blockIdx.x * 256 + threadIdx.x;   // grid 8 x 256 = 2048
    if (t < 1024) {                            // norm_r[m] = sum_l mask[l][m] (coalesced across threads)
        float s = 0.f;
        for (int l = 0; l < 1024; l++) s += mask[(size_t)l * 1024 + t];
        g_norm_r[t] = s;
    } else {                                   // norm_c[l] = sum_m mask[l][m]
        int l = t - 1024;
        const float4* p = (const float4*)(mask + (size_t)l * 1024);
        float s = 0.f;
        for (int m = 0; m < 256; m++) { float4 v = p[m]; s += v.x + v.y + v.z + v.w; }
        g_norm_c[l] = s;
    }
}

// ---------------- K1: pair kernel (LN -> GEMM -> ReLU -> GEMM -> mask -> partial reductions) ----------------
__global__ __launch_bounds__(256, 1)
void pair_kernel(const float* __restrict__ z, const float* __restrict__ mask,
                 const float* __restrict__ lng, const float* __restrict__ lnb,
                 const float* __restrict__ w1, const float* __restrict__ b1,
                 const float* __restrict__ w2, const float* __restrict__ b2) {
    extern __shared__ char sm[];
    __nv_bfloat16* w1s = (__nv_bfloat16*)(sm);
    __nv_bfloat16* w2s = (__nv_bfloat16*)(sm + 34816);
    __nv_bfloat16* at  = (__nv_bfloat16*)(sm + 69632);
    __nv_bfloat16* bt  = (__nv_bfloat16*)(sm + 104448);
    float* accc = (float*)(sm + 139264);
    float* msk  = (float*)(sm + 139776);
    float* lngs = (float*)(sm + 140288);
    float* lnbs = (float*)(sm + 140800);
    float* b1s  = (float*)(sm + 141312);
    float* b2s  = (float*)(sm + 141824);

    const int tid  = threadIdx.x;
    const int w    = tid >> 5;
    const int lane = tid & 31;
    const int g    = lane >> 2;
    const int tc   = lane & 3;
    const int mb   = blockIdx.x;            // 0..7
    const int lb   = blockIdx.y;            // 0..63
    const int m0   = mb * 128;

    // load + convert weights (K-major, matches B-operand layout)
    for (int i = tid; i < 128 * 128; i += 256) {
        int r = i >> 7, c = i & 127;
        w1s[r * PADA + c] = __float2bfloat16(w1[i]);
        w2s[r * PADA + c] = __float2bfloat16(w2[i]);
    }
    if (tid < 128) {
        lngs[tid] = lng[tid]; lnbs[tid] = lnb[tid];
        b1s[tid] = b1[tid];   b2s[tid] = b2[tid];
        accc[tid] = 0.f;
    }

    // per-lane ldmatrix offsets
    const int lane7 = lane & 7;
    const int a_row = (((lane >> 3) & 1) << 3) + lane7;
    const int a_col = ((lane >> 4) & 1) << 3;
    const int b_row = (((lane >> 4) & 1) << 3) + lane7;
    const int b_col = ((lane >> 3) & 1) << 3;

    const uint32_t at_u  = (uint32_t)__cvta_generic_to_shared(at);
    const uint32_t bt_u  = (uint32_t)__cvta_generic_to_shared(bt);
    const uint32_t w1_u  = (uint32_t)__cvta_generic_to_shared(w1s);
    const uint32_t w2_u  = (uint32_t)__cvta_generic_to_shared(w2s);
    const uint32_t a_at  = at_u + (uint32_t)(((16 * w + a_row) * PADA + a_col) * 2);
    const uint32_t a_bt  = bt_u + (uint32_t)(((16 * w + a_row) * PADA + a_col) * 2);
    const uint32_t b_w1  = w1_u + (uint32_t)((b_row * PADA + b_col) * 2);
    const uint32_t b_w2  = w2_u + (uint32_t)((b_row * PADA + b_col) * 2);

    float acc_r[64];
#pragma unroll
    for (int i = 0; i < 64; i++) acc_r[i] = 0.f;

    __syncthreads();

    for (int li = 0; li < LBSZ; ++li) {
        const int l = lb * LBSZ + li;
        const float* zrow = z + ((size_t)l * 1024 + m0) * 128;

        // ---- LayerNorm 128 rows -> bf16 tile 'at' ----
#pragma unroll
        for (int pass = 0; pass < 4; ++pass) {
            int r  = pass * 32 + w * 4 + (lane >> 3);
            int c0 = (lane & 7) * 16;
            const float4* p = (const float4*)(zrow + r * 128 + c0);
            float x[16];
#pragma unroll
            for (int j = 0; j < 4; j++) {
                float4 v = p[j];
                x[4 * j] = v.x; x[4 * j + 1] = v.y; x[4 * j + 2] = v.z; x[4 * j + 3] = v.w;
            }
            float s = 0.f, sq = 0.f;
#pragma unroll
            for (int j = 0; j < 16; j++) { s += x[j]; sq = fmaf(x[j], x[j], sq); }
#pragma unroll
            for (int o = 1; o < 8; o <<= 1) {
                s  += __shfl_xor_sync(0xffffffffu, s,  o);
                sq += __shfl_xor_sync(0xffffffffu, sq, o);
            }
            float mu  = s * (1.f / 128.f);
            float var = fmaf(sq, 1.f / 128.f, -mu * mu);
            float rs  = rsqrtf(var + 1e-5f);
            __nv_bfloat16* arow = at + r * PADA + c0;
#pragma unroll
            for (int j = 0; j < 16; j += 2) {
                float v0 = fmaf((x[j]     - mu) * rs, lngs[c0 + j],     lnbs[c0 + j]);
                float v1 = fmaf((x[j + 1] - mu) * rs, lngs[c0 + j + 1], lnbs[c0 + j + 1]);
                *(__nv_bfloat162*)(arow + j) = __floats2bfloat162_rn(v0, v1);
            }
        }
        if (tid < 128) msk[tid] = mask[(size_t)l * 1024 + m0 + tid];
        __syncthreads();

        // ---- GEMM1: Y1 = LN(z) @ w1^T ----
        float d[64];
#pragma unroll
        for (int i = 0; i < 64; i++) d[i] = 0.f;
        gemm128(a_at, b_w1, d);

        // ---- ReLU(Y1 + b1) -> bf16 tile 'bt' ----
        {
            int row0 = 16 * w + g;
#pragma unroll
            for (int nt = 0; nt < 16; nt++) {
                int col = nt * 8 + tc * 2;
                float bb0 = b1s[col], bb1 = b1s[col + 1];
                float v0 = fmaxf(d[nt * 4 + 0] + bb0, 0.f);
                float v1 = fmaxf(d[nt * 4 + 1] + bb1, 0.f);
                float v2 = fmaxf(d[nt * 4 + 2] + bb0, 0.f);
                float v3 = fmaxf(d[nt * 4 + 3] + bb1, 0.f);
                *(__nv_bfloat162*)(bt + row0 * PADA + col)       = __floats2bfloat162_rn(v0, v1);
                *(__nv_bfloat162*)(bt + (row0 + 8) * PADA + col) = __floats2bfloat162_rn(v2, v3);
            }
        }
        __syncthreads();

        // ---- GEMM2: Y2 = relu @ w2^T ----
#pragma unroll
        for (int i = 0; i < 64; i++) d[i] = 0.f;
        gemm128(a_bt, b_w2, d);

        // ---- epilogue: +b2, *mask, accumulate reductions ----
        float m_lo = msk[16 * w + g];
        float m_hi = msk[16 * w + g + 8];
#pragma unroll
        for (int nt = 0; nt < 16; nt++) {
            int col = nt * 8 + tc * 2;
            float bb0 = b2s[col], bb1 = b2s[col + 1];
            float v0 = (d[nt * 4 + 0] + bb0) * m_lo;
            float v1 = (d[nt * 4 + 1] + bb1) * m_lo;
            float v2 = (d[nt * 4 + 2] + bb0) * m_hi;
            float v3 = (d[nt * 4 + 3] + bb1) * m_hi;
            acc_r[nt * 4 + 0] += v0; acc_r[nt * 4 + 1] += v1;
            acc_r[nt * 4 + 2] += v2; acc_r[nt * 4 + 3] += v3;
            // column (over-m) sums: reduce over g (lane bits 2..4)
            float s0 = v0 + v2, s1 = v1 + v3;
            s0 += __shfl_xor_sync(0xffffffffu, s0, 4);
            s0 += __shfl_xor_sync(0xffffffffu, s0, 8);
            s0 += __shfl_xor_sync(0xffffffffu, s0, 16);
            s1 += __shfl_xor_sync(0xffffffffu, s1, 4);
            s1 += __shfl_xor_sync(0xffffffffu, s1, 8);
            s1 += __shfl_xor_sync(0xffffffffu, s1, 16);
            if (g == 0) {
                atomicAdd(&accc[col],     s0);
                atomicAdd(&accc[col + 1], s1);
            }
        }
        __syncthreads();
        if (tid < 128) {
            g_scratch_c[((size_t)mb * 1024 + l) * 128 + tid] = accc[tid];
            accc[tid] = 0.f;
        }
        __syncthreads();
    }

    // ---- write over-l partials (no atomics: per (l_block, m, c) written exactly once) ----
    {
        int mrow = m0 + 16 * w + g;
#pragma unroll
        for (int nt = 0; nt < 16; nt++) {
            int col = nt * 8 + tc * 2;
            *(float2*)&g_scratch_r[((size_t)lb * 1024 + mrow)     * 128 + col] =
                make_float2(acc_r[nt * 4 + 0], acc_r[nt * 4 + 1]);
            *(float2*)&g_scratch_r[((size_t)lb * 1024 + mrow + 8) * 128 + col] =
                make_float2(acc_r[nt * 4 + 2], acc_r[nt * 4 + 3]);
        }
    }
}

// ---------------- K2: reduce partials + build concat rows (f32) ----------------
__global__ void cat_kernel(const float* __restrict__ s_s_in) {
    int l = blockIdx.x;
    int t = threadIdx.x;       // 256
    if (t < 128) {
        float s = 0.f;
#pragma unroll
        for (int p = 0; p < 8; p++) s += g_scratch_c[((size_t)p * 1024 + l) * 128 + t];
        float n = fmaxf(g_norm_c[l], 1.f);
        g_catf[(size_t)l * 1280 + t] = s / n;
    } else {
        int c = t - 128;
        float s = 0.f;
#pragma unroll
        for (int p = 0; p < 64; p++) s += g_scratch_r[((size_t)p * 1024 + l) * 128 + c];
        float n = fmaxf(g_norm_r[l], 1.f);
        g_catf[(size_t)l * 1280 + 128 + c] = s / n;
    }
    for (int c = t; c < 1024; c += 256)
        g_catf[(size_t)l * 1280 + 256 + c] = s_s_in[(size_t)l * 1024 + c];
}

// ---------------- K3: final projection out = cat @ wc^T + bc (tf32 for accuracy) ----------------
#define PADF 36
__global__ __launch_bounds__(256, 1)
void final_gemm(const float* __restrict__ wc, const float* __restrict__ bc, float* __restrict__ out) {
    __shared__ alignas(16) float atf[128 * PADF];
    __shared__ alignas(16) float btf[128 * PADF];
    const int tid = threadIdx.x, w = tid >> 5, lane = tid & 31;
    const int g = lane >> 2, tc = lane & 3;
    const int l0 = blockIdx.y * 128, d0 = blockIdx.x * 128;

    float d[64];
#pragma unroll
    for (int i = 0; i < 64; i++) d[i] = 0.f;

    for (int kc = 0; kc < 40; ++kc) {
        int k0 = kc * 32;
#pragma unroll
        for (int it = 0; it < 4; it++) {
            int r = it * 32 + (tid >> 3);
            int cg = (tid & 7) * 4;
            *(float4*)(atf + r * PADF + cg) = *(const float4*)(g_catf + (size_t)(l0 + r) * 1280 + k0 + cg);
            *(float4*)(btf + r * PADF + cg) = *(const float4*)(wc     + (size_t)(d0 + r) * 1280 + k0 + cg);
        }
        __syncthreads();
#pragma unroll
        for (int k = 0; k < 4; k++) {
            int kk = k * 8;
            uint32_t a0 = f2tf(atf[(16 * w + g)     * PADF + kk + tc]);
            uint32_t a1 = f2tf(atf[(16 * w + 8 + g) * PADF + kk + tc]);
            uint32_t a2 = f2tf(atf[(16 * w + g)     * PADF + kk + tc + 4]);
            uint32_t a3 = f2tf(atf[(16 * w + 8 + g) * PADF + kk + tc + 4]);
#pragma unroll
            for (int nt = 0; nt < 16; nt++) {
                uint32_t b0 = f2tf(btf[(nt * 8 + g) * PADF + kk + tc]);
                uint32_t b1 = f2tf(btf[(nt * 8 + g) * PADF + kk + tc + 4]);
                mma_tf32(d + nt * 4, a0, a1, a2, a3, b0, b1);
            }
        }
        __syncthreads();
    }

    int row = l0 + 16 * w + g;
#pragma unroll
    for (int nt = 0; nt < 16; nt++) {
        int col = d0 + nt * 8 + tc * 2;
        float bb0 = bc[col], bb1 = bc[col + 1];
        *(float2*)&out[(size_t)row * 1024 + col]       = make_float2(d[nt * 4 + 0] + bb0, d[nt * 4 + 1] + bb1);
        *(float2*)&out[(size_t)(row + 8) * 1024 + col] = make_float2(d[nt * 4 + 2] + bb0, d[nt * 4 + 3] + bb1);
    }
}

// ---------------- launch ----------------
extern "C" void kernel_launch(void* const* d_in, const int* in_sizes, int n_in,
                              void* d_out, int out_size) {
    const float* s_z    = (const float*)d_in[0];
    const float* s_s_in = (const float*)d_in[1];
    const float* mask   = (const float*)d_in[2];
    const float* ln_g   = (const float*)d_in[3];
    const float* ln_b   = (const float*)d_in[4];
    const float* w1     = (const float*)d_in[5];
    const float* b1     = (const float*)d_in[6];
    const float* w2     = (const float*)d_in[7];
    const float* b2     = (const float*)d_in[8];
    const float* wc     = (const float*)d_in[9];
    const float* bc     = (const float*)d_in[10];
    float* out = (float*)d_out;

    cudaFuncSetAttribute(pair_kernel, cudaFuncAttributeMaxDynamicSharedMemorySize, SMEM_PAIR);

    norm_kernel<<<8, 256>>>(mask);
    pair_kernel<<<dim3(8, NLB), 256, SMEM_PAIR>>>(s_z, mask, ln_g, ln_b, w1, b1, w2, b2);
    cat_kernel<<<1024, 256>>>(s_s_in);
    final_gemm<<<dim3(8, 8), 256>>>(wc, bc, out);
}

// round 3
// speedup vs baseline: 1.3615x; 1.3615x over previous
#include <cuda_runtime.h>
#include <cuda_bf16.h>
#include <cstdint>

// Problem constants (fixed shapes: B=1, L=1024, C_Z=128, C_S=1024, C_S_OUT=1024)
#define PADA 136            // bf16 elems per smem row (128 + 8 pad), ldmatrix conflict-free
#define ZPAD 132            // f32 elems per z-tile smem row (128 + 4 pad)
#define NLB  64
#define LBSZ 16

// smem layout (bytes) for pair kernel
#define OFF_W1   0            // 128*136*2 = 34816
#define OFF_AT   34816        // 34816
#define OFF_Z    69632        // 2*128*132*4 = 135168
#define OFF_MSK  204800       // 2*128*4 = 1024
#define OFF_ACCC 205824       // 512
#define OFF_LNG  206336
#define OFF_LNB  206848
#define OFF_B1   207360
#define SMEM_PAIR 207872

// ---------------- device scratch ----------------
__device__ float g_scratch_c[8ull  * 1024ull * 128ull];   // [m_block][l][k]
__device__ float g_scratch_r[64ull * 1024ull * 128ull];   // [l_block][m][k]
__device__ float g_catf[1024ull * 1280ull];               // concat rows (f32)
__device__ float g_norm_c[1024];                          // raw mask row-sums
__device__ float g_norm_r[1024];                          // raw mask col-sums

// ---------------- MMA helpers ----------------
__device__ __forceinline__ void ldsm4(uint32_t &r0, uint32_t &r1, uint32_t &r2, uint32_t &r3, uint32_t addr) {
    asm volatile("ldmatrix.sync.aligned.m8n8.x4.shared.b16 {%0,%1,%2,%3}, [%4];"
                 : "=r"(r0), "=r"(r1), "=r"(r2), "=r"(r3) : "r"(addr));
}
__device__ __forceinline__ void mma_bf16(float* d, uint32_t a0, uint32_t a1, uint32_t a2, uint32_t a3,
                                         uint32_t b0, uint32_t b1) {
    asm volatile("mma.sync.aligned.m16n8k16.row.col.f32.bf16.bf16.f32 "
                 "{%0,%1,%2,%3}, {%4,%5,%6,%7}, {%8,%9}, {%0,%1,%2,%3};"
                 : "+f"(d[0]), "+f"(d[1]), "+f"(d[2]), "+f"(d[3])
                 : "r"(a0), "r"(a1), "r"(a2), "r"(a3), "r"(b0), "r"(b1));
}
__device__ __forceinline__ void mma_tf32(float* d, uint32_t a0, uint32_t a1, uint32_t a2, uint32_t a3,
                                         uint32_t b0, uint32_t b1) {
    asm volatile("mma.sync.aligned.m16n8k8.row.col.f32.tf32.tf32.f32 "
                 "{%0,%1,%2,%3}, {%4,%5,%6,%7}, {%8,%9}, {%0,%1,%2,%3};"
                 : "+f"(d[0]), "+f"(d[1]), "+f"(d[2]), "+f"(d[3])
                 : "r"(a0), "r"(a1), "r"(a2), "r"(a3), "r"(b0), "r"(b1));
}
__device__ __forceinline__ uint32_t f2tf(float f) {
    uint32_t r; asm("cvt.rna.tf32.f32 %0, %1;" : "=r"(r) : "f"(f)); return r;
}
__device__ __forceinline__ void cpa16(uint32_t dst, const void* src) {
    asm volatile("cp.async.cg.shared.global [%0], [%1], 16;" :: "r"(dst), "l"(src));
}

// 128x128x128 bf16 GEMM tile: D(128m x 128n) += A(128x128,K-major) * B(128n x 128k,K-major)^T
__device__ __forceinline__ void gemm128(uint32_t abase, uint32_t bbase, float* d) {
#pragma unroll
    for (int k = 0; k < 8; k++) {
        uint32_t a0, a1, a2, a3;
        ldsm4(a0, a1, a2, a3, abase + k * 32);
#pragma unroll
        for (int ntp = 0; ntp < 8; ntp++) {
            uint32_t b0, b1, b2, b3;
            ldsm4(b0, b1, b2, b3, bbase + ntp * (16 * PADA * 2) + k * 32);
            mma_bf16(d + ntp * 8,     a0, a1, a2, a3, b0, b1);
            mma_bf16(d + ntp * 8 + 4, a0, a1, a2, a3, b2, b3);
        }
    }
}

// ---------------- K0: raw masked-norm vectors ----------------
__global__ void norm_kernel(const float* __restrict__ mask) {
    int t = blockIdx.x * 256 + threadIdx.x;   // grid 8 x 256 = 2048
    if (t < 1024) {                            // norm_r[m] = sum_l mask[l][m]
        float s = 0.f;
#pragma unroll 8
        for (int l = 0; l < 1024; l++) s += mask[(size_t)l * 1024 + t];
        g_norm_r[t] = s;
    } else {                                   // norm_c[l] = sum_m mask[l][m]
        int l = t - 1024;
        const float4* p = (const float4*)(mask + (size_t)l * 1024);
        float s = 0.f;
#pragma unroll 8
        for (int m = 0; m < 256; m++) { float4 v = p[m]; s += v.x + v.y + v.z + v.w; }
        g_norm_c[l] = s;
    }
}

// ---------------- K1: pair kernel (LN -> GEMM1 -> relu/mask -> partial reductions) ----------------
__global__ __launch_bounds__(256, 1)
void pair_kernel(const float* __restrict__ z, const float* __restrict__ mask,
                 const float* __restrict__ lng, const float* __restrict__ lnb,
                 const float* __restrict__ w1, const float* __restrict__ b1) {
    extern __shared__ char sm[];
    __nv_bfloat16* w1s = (__nv_bfloat16*)(sm + OFF_W1);
    __nv_bfloat16* at  = (__nv_bfloat16*)(sm + OFF_AT);
    float* zbuf = (float*)(sm + OFF_Z);
    float* mskb = (float*)(sm + OFF_MSK);
    float* accc = (float*)(sm + OFF_ACCC);
    float* lngs = (float*)(sm + OFF_LNG);
    float* lnbs = (float*)(sm + OFF_LNB);
    float* b1s  = (float*)(sm + OFF_B1);

    const int tid  = threadIdx.x;
    const int w    = tid >> 5;
    const int lane = tid & 31;
    const int g    = lane >> 2;
    const int tc   = lane & 3;
    const int mb   = blockIdx.x;            // 0..7
    const int lb   = blockIdx.y;            // 0..63
    const int m0   = mb * 128;

    // load + convert w1 (K-major, matches B-operand layout)
    for (int i = tid; i < 128 * 128; i += 256) {
        int r = i >> 7, c = i & 127;
        w1s[r * PADA + c] = __float2bfloat16(w1[i]);
    }
    if (tid < 128) {
        lngs[tid] = lng[tid]; lnbs[tid] = lnb[tid];
        b1s[tid] = b1[tid];   accc[tid] = 0.f;
    }

    // per-lane ldmatrix offsets
    const int lane7 = lane & 7;
    const int a_row = (((lane >> 3) & 1) << 3) + lane7;
    const int a_col = ((lane >> 4) & 1) << 3;
    const int b_row = (((lane >> 4) & 1) << 3) + lane7;
    const int b_col = ((lane >> 3) & 1) << 3;

    const uint32_t at_u  = (uint32_t)__cvta_generic_to_shared(at);
    const uint32_t w1_u  = (uint32_t)__cvta_generic_to_shared(w1s);
    const uint32_t zb_u  = (uint32_t)__cvta_generic_to_shared(zbuf);
    const uint32_t msk_u = (uint32_t)__cvta_generic_to_shared(mskb);
    const uint32_t a_at  = at_u + (uint32_t)(((16 * w + a_row) * PADA + a_col) * 2);
    const uint32_t b_w1  = w1_u + (uint32_t)((b_row * PADA + b_col) * 2);

    float acc_r[64];
#pragma unroll
    for (int i = 0; i < 64; i++) acc_r[i] = 0.f;

    // async-copy issue for one l
    auto issue = [&](int l, int buf) {
        const float* zsrc = z + ((size_t)l * 1024 + m0) * 128;
        uint32_t zdst = zb_u + (uint32_t)(buf * (128 * ZPAD * 4));
#pragma unroll
        for (int i = 0; i < 16; i++) {
            int id = tid + i * 256;
            int r = id >> 5, c = (id & 31) * 4;
            cpa16(zdst + (uint32_t)((r * ZPAD + c) * 4), zsrc + r * 128 + c);
        }
        if (tid < 32)
            cpa16(msk_u + (uint32_t)(buf * 512 + tid * 16), mask + (size_t)l * 1024 + m0 + tid * 4);
        asm volatile("cp.async.commit_group;");
    };

    issue(lb * LBSZ, 0);

    for (int li = 0; li < LBSZ; ++li) {
        const int l = lb * LBSZ + li;
        const int buf = li & 1;

        if (li + 1 < LBSZ) {
            issue(l + 1, buf ^ 1);
            asm volatile("cp.async.wait_group 1;");
        } else {
            asm volatile("cp.async.wait_group 0;");
        }
        __syncthreads();   // everyone's cp.async data visible

        // ---- LayerNorm 128 rows from zbuf -> bf16 tile 'at' ----
        const float* zb = zbuf + (size_t)buf * (128 * ZPAD);
#pragma unroll
        for (int pass = 0; pass < 4; ++pass) {
            int r  = pass * 32 + w * 4 + (lane >> 3);
            int c0 = (lane & 7) * 4;
            const float* base = zb + r * ZPAD + c0;
            float x[16];
#pragma unroll
            for (int j = 0; j < 4; j++) {
                float4 v = *(const float4*)(base + j * 32);
                x[4 * j] = v.x; x[4 * j + 1] = v.y; x[4 * j + 2] = v.z; x[4 * j + 3] = v.w;
            }
            float s = 0.f, sq = 0.f;
#pragma unroll
            for (int j = 0; j < 16; j++) { s += x[j]; sq = fmaf(x[j], x[j], sq); }
#pragma unroll
            for (int o = 1; o < 8; o <<= 1) {
                s  += __shfl_xor_sync(0xffffffffu, s,  o);
                sq += __shfl_xor_sync(0xffffffffu, sq, o);
            }
            float mu  = s * (1.f / 128.f);
            float var = fmaf(sq, 1.f / 128.f, -mu * mu);
            float rs  = rsqrtf(var + 1e-5f);
            __nv_bfloat16* arow = at + r * PADA;
#pragma unroll
            for (int j = 0; j < 4; j++) {
                int cc = c0 + j * 32;
                float v0 = fmaf((x[4 * j]     - mu) * rs, lngs[cc],     lnbs[cc]);
                float v1 = fmaf((x[4 * j + 1] - mu) * rs, lngs[cc + 1], lnbs[cc + 1]);
                float v2 = fmaf((x[4 * j + 2] - mu) * rs, lngs[cc + 2], lnbs[cc + 2]);
                float v3 = fmaf((x[4 * j + 3] - mu) * rs, lngs[cc + 3], lnbs[cc + 3]);
                *(__nv_bfloat162*)(arow + cc)     = __floats2bfloat162_rn(v0, v1);
                *(__nv_bfloat162*)(arow + cc + 2) = __floats2bfloat162_rn(v2, v3);
            }
        }
        __syncthreads();   // 'at' ready

        // ---- GEMM1: Y1 = LN(z) @ w1^T ----
        float d[64];
#pragma unroll
        for (int i = 0; i < 64; i++) d[i] = 0.f;
        gemm128(a_at, b_w1, d);

        // ---- epilogue: R = relu(Y1+b1), v = mask*R, accumulate reductions ----
        const float* mrow = mskb + buf * 128;
        float m_lo = mrow[16 * w + g];
        float m_hi = mrow[16 * w + g + 8];
#pragma unroll
        for (int nt = 0; nt < 16; nt++) {
            int col = nt * 8 + tc * 2;
            float bb0 = b1s[col], bb1 = b1s[col + 1];
            float v0 = fmaxf(d[nt * 4 + 0] + bb0, 0.f) * m_lo;
            float v1 = fmaxf(d[nt * 4 + 1] + bb1, 0.f) * m_lo;
            float v2 = fmaxf(d[nt * 4 + 2] + bb0, 0.f) * m_hi;
            float v3 = fmaxf(d[nt * 4 + 3] + bb1, 0.f) * m_hi;
            acc_r[nt * 4 + 0] += v0; acc_r[nt * 4 + 1] += v1;
            acc_r[nt * 4 + 2] += v2; acc_r[nt * 4 + 3] += v3;
            float s0 = v0 + v2, s1 = v1 + v3;
            s0 += __shfl_xor_sync(0xffffffffu, s0, 4);
            s0 += __shfl_xor_sync(0xffffffffu, s0, 8);
            s0 += __shfl_xor_sync(0xffffffffu, s0, 16);
            s1 += __shfl_xor_sync(0xffffffffu, s1, 4);
            s1 += __shfl_xor_sync(0xffffffffu, s1, 8);
            s1 += __shfl_xor_sync(0xffffffffu, s1, 16);
            if (g == 0) {
                atomicAdd(&accc[col],     s0);
                atomicAdd(&accc[col + 1], s1);
            }
        }
        __syncthreads();   // atomics done
        if (tid < 128) {
            g_scratch_c[((size_t)mb * 1024 + l) * 128 + tid] = accc[tid];
            accc[tid] = 0.f;
        }
        // no extra sync: next use of accc is after two barriers next iter
    }

    // ---- write over-l partials ----
    {
        int mrow = m0 + 16 * w + g;
#pragma unroll
        for (int nt = 0; nt < 16; nt++) {
            int col = nt * 8 + tc * 2;
            *(float2*)&g_scratch_r[((size_t)lb * 1024 + mrow)     * 128 + col] =
                make_float2(acc_r[nt * 4 + 0], acc_r[nt * 4 + 1]);
            *(float2*)&g_scratch_r[((size_t)lb * 1024 + mrow + 8) * 128 + col] =
                make_float2(acc_r[nt * 4 + 2], acc_r[nt * 4 + 3]);
        }
    }
}

// ---------------- K2: reduce partials, apply deferred GEMM2 (fp32 dots), build concat ----------------
__global__ __launch_bounds__(256, 4)
void cat_kernel(const float* __restrict__ s_s_in, const float* __restrict__ w2,
                const float* __restrict__ b2) {
    __shared__ alignas(16) float Sc[128];
    __shared__ alignas(16) float Sr[128];
    int l = blockIdx.x;
    int t = threadIdx.x;
    if (t < 128) {
        float s = 0.f;
#pragma unroll
        for (int p = 0; p < 8; p++) s += g_scratch_c[((size_t)p * 1024 + l) * 128 + t];
        Sc[t] = s;
    } else {
        int c = t - 128;
        float s = 0.f;
#pragma unroll
        for (int p = 0; p < 64; p++) s += g_scratch_r[((size_t)p * 1024 + l) * 128 + c];
        Sr[c] = s;
    }
    __syncthreads();

    // deferred GEMM2: t_c[d] = S @ w2[d,:]  (+ masksum*b2), then /clip(masksum,1)
    int c = t & 127;
    const float4* wrow = (const float4*)(w2 + (size_t)c * 128);
    const float4* Sv   = (const float4*)((t < 128) ? Sc : Sr);
    float s = 0.f;
#pragma unroll 8
    for (int kk = 0; kk < 32; kk++) {
        float4 wv = wrow[kk], sv = Sv[kk];
        s = fmaf(wv.x, sv.x, s); s = fmaf(wv.y, sv.y, s);
        s = fmaf(wv.z, sv.z, s); s = fmaf(wv.w, sv.w, s);
    }
    float ns = (t < 128) ? g_norm_c[l] : g_norm_r[l];
    float val = (s + ns * b2[c]) / fmaxf(ns, 1.f);
    g_catf[(size_t)l * 1280 + ((t < 128) ? 0 : 128) + c] = val;

    for (int cc = t; cc < 1024; cc += 256)
        g_catf[(size_t)l * 1280 + 256 + cc] = s_s_in[(size_t)l * 1024 + cc];
}

// ---------------- K3: final projection out = cat @ wc^T + bc (tf32), 64x128 tiles ----------------
#define PADF 36
__global__ __launch_bounds__(256, 1)
void final_gemm(const float* __restrict__ wc, const float* __restrict__ bc, float* __restrict__ out) {
    __shared__ uint32_t atf[64 * PADF];
    __shared__ uint32_t btf[128 * PADF];
    const int tid = threadIdx.x, w = tid >> 5, lane = tid & 31;
    const int g = lane >> 2, tc = lane & 3;
    const int wr = w & 3, cg = w >> 2;
    const int l0 = blockIdx.y * 64, d0 = blockIdx.x * 128;

    float d[32];
#pragma unroll
    for (int i = 0; i < 32; i++) d[i] = 0.f;

    for (int kc = 0; kc < 40; ++kc) {
        int k0 = kc * 32;
        int c = (tid & 7) * 4;
#pragma unroll
        for (int it = 0; it < 2; it++) {
            int r = it * 32 + (tid >> 3);
            float4 v = *(const float4*)(g_catf + (size_t)(l0 + r) * 1280 + k0 + c);
            uint32_t* p = atf + r * PADF + c;
            p[0] = f2tf(v.x); p[1] = f2tf(v.y); p[2] = f2tf(v.z); p[3] = f2tf(v.w);
        }
#pragma unroll
        for (int it = 0; it < 4; it++) {
            int r = it * 32 + (tid >> 3);
            float4 v = *(const float4*)(wc + (size_t)(d0 + r) * 1280 + k0 + c);
            uint32_t* p = btf + r * PADF + c;
            p[0] = f2tf(v.x); p[1] = f2tf(v.y); p[2] = f2tf(v.z); p[3] = f2tf(v.w);
        }
        __syncthreads();
#pragma unroll
        for (int k = 0; k < 4; k++) {
            int kk = k * 8;
            uint32_t a0 = atf[(16 * wr + g)     * PADF + kk + tc];
            uint32_t a1 = atf[(16 * wr + 8 + g) * PADF + kk + tc];
            uint32_t a2 = atf[(16 * wr + g)     * PADF + kk + tc + 4];
            uint32_t a3 = atf[(16 * wr + 8 + g) * PADF + kk + tc + 4];
#pragma unroll
            for (int nt = 0; nt < 8; nt++) {
                int row = cg * 64 + nt * 8 + g;
                uint32_t b0 = btf[row * PADF + kk + tc];
                uint32_t b1 = btf[row * PADF + kk + tc + 4];
                mma_tf32(d + nt * 4, a0, a1, a2, a3, b0, b1);
            }
        }
        __syncthreads();
    }

    int row = l0 + 16 * wr + g;
#pragma unroll
    for (int nt = 0; nt < 8; nt++) {
        int col = d0 + cg * 64 + nt * 8 + tc * 2;
        float bb0 = bc[col], bb1 = bc[col + 1];
        *(float2*)&out[(size_t)row * 1024 + col]       = make_float2(d[nt * 4 + 0] + bb0, d[nt * 4 + 1] + bb1);
        *(float2*)&out[(size_t)(row + 8) * 1024 + col] = make_float2(d[nt * 4 + 2] + bb0, d[nt * 4 + 3] + bb1);
    }
}

// ---------------- launch ----------------
extern "C" void kernel_launch(void* const* d_in, const int* in_sizes, int n_in,
                              void* d_out, int out_size) {
    const float* s_z    = (const float*)d_in[0];
    const float* s_s_in = (const float*)d_in[1];
    const float* mask   = (const float*)d_in[2];
    const float* ln_g   = (const float*)d_in[3];
    const float* ln_b   = (const float*)d_in[4];
    const float* w1     = (const float*)d_in[5];
    const float* b1     = (const float*)d_in[6];
    const float* w2     = (const float*)d_in[7];
    const float* b2     = (const float*)d_in[8];
    const float* wc     = (const float*)d_in[9];
    const float* bc     = (const float*)d_in[10];
    float* out = (float*)d_out;

    cudaFuncSetAttribute(pair_kernel, cudaFuncAttributeMaxDynamicSharedMemorySize, SMEM_PAIR);

    norm_kernel<<<8, 256>>>(mask);
    pair_kernel<<<dim3(8, NLB), 256, SMEM_PAIR>>>(s_z, mask, ln_g, ln_b, w1, b1);
    cat_kernel<<<1024, 256>>>(s_s_in, w2, b2);
    final_gemm<<<dim3(8, 16), 256>>>(wc, bc, out);
}

// round 6
// speedup vs baseline: 1.9943x; 1.4648x over previous
#include <cuda_runtime.h>
#include <cuda_bf16.h>
#include <cstdint>

// Problem constants (fixed shapes: B=1, L=1024, C_Z=128, C_S=1024, C_S_OUT=1024)
#define PADA 136            // bf16 elems per smem row (128 + 8 pad), ldmatrix conflict-free
#define ZPAD 132            // f32 elems per z-tile smem row (128 + 4 pad)
#define NLB  16
#define LBSZ 64

// smem layout (bytes) for pair kernel
#define OFF_W1   0            // 128*136*2 = 34816
#define OFF_AT   34816        // 34816
#define OFF_Z    69632        // 2*128*132*4 = 135168
#define OFF_MSK  204800       // 2*128*4 = 1024
#define OFF_PART 205824       // 2*128*4 = 1024
#define OFF_LNG  206848
#define OFF_LNB  207360
#define OFF_B1   207872
#define SMEM_PAIR 208384

// ---------------- device scratch ----------------
__device__ float g_scratch_c[8ull  * 1024ull * 128ull];   // [m_block][l][k]
__device__ float g_scratch_r[16ull * 1024ull * 128ull];   // [l_block][m][k]
__device__ float g_catf[1024ull * 1280ull];               // concat rows (f32)
__device__ float g_norm_c[1024];
__device__ float g_norm_r[1024];

// ---------------- MMA helpers ----------------
__device__ __forceinline__ void ldsm4(uint32_t &r0, uint32_t &r1, uint32_t &r2, uint32_t &r3, uint32_t addr) {
    asm volatile("ldmatrix.sync.aligned.m8n8.x4.shared.b16 {%0,%1,%2,%3}, [%4];"
                 : "=r"(r0), "=r"(r1), "=r"(r2), "=r"(r3) : "r"(addr));
}
__device__ __forceinline__ void mma_bf16(float* d, uint32_t a0, uint32_t a1, uint32_t a2, uint32_t a3,
                                         uint32_t b0, uint32_t b1) {
    asm volatile("mma.sync.aligned.m16n8k16.row.col.f32.bf16.bf16.f32 "
                 "{%0,%1,%2,%3}, {%4,%5,%6,%7}, {%8,%9}, {%0,%1,%2,%3};"
                 : "+f"(d[0]), "+f"(d[1]), "+f"(d[2]), "+f"(d[3])
                 : "r"(a0), "r"(a1), "r"(a2), "r"(a3), "r"(b0), "r"(b1));
}
__device__ __forceinline__ void mma_tf32(float* d, uint32_t a0, uint32_t a1, uint32_t a2, uint32_t a3,
                                         uint32_t b0, uint32_t b1) {
    asm volatile("mma.sync.aligned.m16n8k8.row.col.f32.tf32.tf32.f32 "
                 "{%0,%1,%2,%3}, {%4,%5,%6,%7}, {%8,%9}, {%0,%1,%2,%3};"
                 : "+f"(d[0]), "+f"(d[1]), "+f"(d[2]), "+f"(d[3])
                 : "r"(a0), "r"(a1), "r"(a2), "r"(a3), "r"(b0), "r"(b1));
}
__device__ __forceinline__ uint32_t f2tf(float f) {
    uint32_t r; asm("cvt.rna.tf32.f32 %0, %1;" : "=r"(r) : "f"(f)); return r;
}
__device__ __forceinline__ void cpa16(uint32_t dst, const void* src) {
    asm volatile("cp.async.cg.shared.global [%0], [%1], 16;" :: "r"(dst), "l"(src));
}

// 128x128x128 bf16 GEMM tile
__device__ __forceinline__ void gemm128(uint32_t abase, uint32_t bbase, float* d) {
#pragma unroll
    for (int k = 0; k < 8; k++) {
        uint32_t a0, a1, a2, a3;
        ldsm4(a0, a1, a2, a3, abase + k * 32);
#pragma unroll
        for (int ntp = 0; ntp < 8; ntp++) {
            uint32_t b0, b1, b2, b3;
            ldsm4(b0, b1, b2, b3, bbase + ntp * (16 * PADA * 2) + k * 32);
            mma_bf16(d + ntp * 8,     a0, a1, a2, a3, b0, b1);
            mma_bf16(d + ntp * 8 + 4, a0, a1, a2, a3, b2, b3);
        }
    }
}

// ---------------- K0: raw masked-norm vectors ----------------
__global__ void norm_kernel(const float* __restrict__ mask) {
    int t = blockIdx.x * 256 + threadIdx.x;
    if (t < 1024) {
        float s = 0.f;
#pragma unroll 8
        for (int l = 0; l < 1024; l++) s += mask[(size_t)l * 1024 + t];
        g_norm_r[t] = s;
    } else {
        int l = t - 1024;
        const float4* p = (const float4*)(mask + (size_t)l * 1024);
        float s = 0.f;
#pragma unroll 8
        for (int m = 0; m < 256; m++) { float4 v = p[m]; s += v.x + v.y + v.z + v.w; }
        g_norm_c[l] = s;
    }
}

// ---------------- K1: pair kernel ----------------
__global__ __launch_bounds__(256, 1)
void pair_kernel(const float* __restrict__ z, const float* __restrict__ mask,
                 const float* __restrict__ lng, const float* __restrict__ lnb,
                 const float* __restrict__ w1, const float* __restrict__ b1) {
    extern __shared__ char sm[];
    __nv_bfloat16* w1s = (__nv_bfloat16*)(sm + OFF_W1);
    __nv_bfloat16* at  = (__nv_bfloat16*)(sm + OFF_AT);
    float* zbuf = (float*)(sm + OFF_Z);
    float* mskb = (float*)(sm + OFF_MSK);
    float* part = (float*)(sm + OFF_PART);
    float* lngs = (float*)(sm + OFF_LNG);
    float* lnbs = (float*)(sm + OFF_LNB);
    float* b1s  = (float*)(sm + OFF_B1);

    const int tid  = threadIdx.x;
    const int w    = tid >> 5;
    const int lane = tid & 31;
    const int g    = lane >> 2;
    const int tc   = lane & 3;
    const int mb   = blockIdx.x;            // 0..7
    const int lb   = blockIdx.y;            // 0..15
    const int m0   = mb * 128;

    for (int i = tid; i < 128 * 128; i += 256) {
        int r = i >> 7, c = i & 127;
        w1s[r * PADA + c] = __float2bfloat16(w1[i]);
    }
    if (tid < 128) {
        lngs[tid] = lng[tid]; lnbs[tid] = lnb[tid];
        b1s[tid] = b1[tid];
    }

    const int lane7 = lane & 7;
    const int a_row = (((lane >> 3) & 1) << 3) + lane7;
    const int a_col = ((lane >> 4) & 1) << 3;
    const int b_row = (((lane >> 4) & 1) << 3) + lane7;
    const int b_col = ((lane >> 3) & 1) << 3;

    const uint32_t at_u  = (uint32_t)__cvta_generic_to_shared(at);
    const uint32_t w1_u  = (uint32_t)__cvta_generic_to_shared(w1s);
    const uint32_t zb_u  = (uint32_t)__cvta_generic_to_shared(zbuf);
    const uint32_t msk_u = (uint32_t)__cvta_generic_to_shared(mskb);
    const uint32_t a_at  = at_u + (uint32_t)(((16 * w + a_row) * PADA + a_col) * 2);
    const uint32_t b_w1  = w1_u + (uint32_t)((b_row * PADA + b_col) * 2);

    float acc_r[64];
#pragma unroll
    for (int i = 0; i < 64; i++) acc_r[i] = 0.f;

    auto issue = [&](int l, int buf) {
        const float* zsrc = z + ((size_t)l * 1024 + m0) * 128;
        uint32_t zdst = zb_u + (uint32_t)(buf * (128 * ZPAD * 4));
#pragma unroll
        for (int i = 0; i < 16; i++) {
            int id = tid + i * 256;
            int r = id >> 5, c = (id & 31) * 4;
            cpa16(zdst + (uint32_t)((r * ZPAD + c) * 4), zsrc + r * 128 + c);
        }
        if (tid < 32)
            cpa16(msk_u + (uint32_t)(buf * 512 + tid * 16), mask + (size_t)l * 1024 + m0 + tid * 4);
        asm volatile("cp.async.commit_group;");
    };

    issue(lb * LBSZ, 0);

    for (int li = 0; li < LBSZ; ++li) {
        const int l = lb * LBSZ + li;
        const int buf = li & 1;

        if (li + 1 < LBSZ) {
            issue(l + 1, buf ^ 1);
            asm volatile("cp.async.wait_group 1;");
        } else {
            asm volatile("cp.async.wait_group 0;");
        }
        __syncthreads();   // z[buf] + mask ready

        // ---- LayerNorm 128 rows from zbuf -> bf16 tile 'at' ----
        float* vbuf = zbuf + (size_t)buf * (128 * ZPAD);
#pragma unroll
        for (int pass = 0; pass < 4; ++pass) {
            int r  = pass * 32 + w * 4 + (lane >> 3);
            int c0 = (lane & 7) * 4;
            const float* base = vbuf + r * ZPAD + c0;
            float x[16];
#pragma unroll
            for (int j = 0; j < 4; j++) {
                float4 v = *(const float4*)(base + j * 32);
                x[4 * j] = v.x; x[4 * j + 1] = v.y; x[4 * j + 2] = v.z; x[4 * j + 3] = v.w;
            }
            float s = 0.f, sq = 0.f;
#pragma unroll
            for (int j = 0; j < 16; j++) { s += x[j]; sq = fmaf(x[j], x[j], sq); }
#pragma unroll
            for (int o = 1; o < 8; o <<= 1) {
                s  += __shfl_xor_sync(0xffffffffu, s,  o);
                sq += __shfl_xor_sync(0xffffffffu, sq, o);
            }
            float mu  = s * (1.f / 128.f);
            float var = fmaf(sq, 1.f / 128.f, -mu * mu);
            float rs  = rsqrtf(var + 1e-5f);
            __nv_bfloat16* arow = at + r * PADA;
#pragma unroll
            for (int j = 0; j < 4; j++) {
                int cc = c0 + j * 32;
                float v0 = fmaf((x[4 * j]     - mu) * rs, lngs[cc],     lnbs[cc]);
                float v1 = fmaf((x[4 * j + 1] - mu) * rs, lngs[cc + 1], lnbs[cc + 1]);
                float v2 = fmaf((x[4 * j + 2] - mu) * rs, lngs[cc + 2], lnbs[cc + 2]);
                float v3 = fmaf((x[4 * j + 3] - mu) * rs, lngs[cc + 3], lnbs[cc + 3]);
                *(__nv_bfloat162*)(arow + cc)     = __floats2bfloat162_rn(v0, v1);
                *(__nv_bfloat162*)(arow + cc + 2) = __floats2bfloat162_rn(v2, v3);
            }
        }
        __syncthreads();   // 'at' ready; zbuf[buf] now dead -> reuse as V buffer

        // ---- GEMM1 ----
        float d[64];
#pragma unroll
        for (int i = 0; i < 64; i++) d[i] = 0.f;
        gemm128(a_at, b_w1, d);

        // ---- epilogue: v = mask*relu(Y1+b1); accumulate over-l in regs; stash V tile ----
        const float* mrow = mskb + buf * 128;
        float m_lo = mrow[16 * w + g];
        float m_hi = mrow[16 * w + g + 8];
        float* vrow_lo = vbuf + (16 * w + g) * ZPAD;
        float* vrow_hi = vbuf + (16 * w + 8 + g) * ZPAD;
#pragma unroll
        for (int nt = 0; nt < 16; nt++) {
            int col = nt * 8 + tc * 2;
            float bb0 = b1s[col], bb1 = b1s[col + 1];
            float v0 = fmaxf(d[nt * 4 + 0] + bb0, 0.f) * m_lo;
            float v1 = fmaxf(d[nt * 4 + 1] + bb1, 0.f) * m_lo;
            float v2 = fmaxf(d[nt * 4 + 2] + bb0, 0.f) * m_hi;
            float v3 = fmaxf(d[nt * 4 + 3] + bb1, 0.f) * m_hi;
            acc_r[nt * 4 + 0] += v0; acc_r[nt * 4 + 1] += v1;
            acc_r[nt * 4 + 2] += v2; acc_r[nt * 4 + 3] += v3;
            *(float2*)(vrow_lo + col) = make_float2(v0, v1);
            *(float2*)(vrow_hi + col) = make_float2(v2, v3);
        }
        __syncthreads();   // V tile complete

        // ---- column sums over m (smem transpose reduction, no shuffles/atomics) ----
        {
            int col = tid & 127, half = tid >> 7;
            const float* p = vbuf + (size_t)half * 64 * ZPAD + col;
            float s = 0.f;
#pragma unroll 16
            for (int r = 0; r < 64; r++) s += p[(size_t)r * ZPAD];
            part[half * 128 + col] = s;
        }
        __syncthreads();
        if (tid < 128)
            g_scratch_c[((size_t)mb * 1024 + l) * 128 + tid] = part[tid] + part[128 + tid];
        // next vbuf write is after >=1 barrier next iter; cp.async into vbuf is issued
        // post-barrier, after all reads above completed
    }

    // ---- over-l partials ----
    {
        int mrow = m0 + 16 * w + g;
#pragma unroll
        for (int nt = 0; nt < 16; nt++) {
            int col = nt * 8 + tc * 2;
            *(float2*)&g_scratch_r[((size_t)lb * 1024 + mrow)     * 128 + col] =
                make_float2(acc_r[nt * 4 + 0], acc_r[nt * 4 + 1]);
            *(float2*)&g_scratch_r[((size_t)lb * 1024 + mrow + 8) * 128 + col] =
                make_float2(acc_r[nt * 4 + 2], acc_r[nt * 4 + 3]);
        }
    }
}

// ---------------- K2: reduce partials, deferred GEMM2, build concat ----------------
__global__ __launch_bounds__(256, 4)
void cat_kernel(const float* __restrict__ s_s_in, const float* __restrict__ w2,
                const float* __restrict__ b2) {
    __shared__ alignas(16) float Sc[128];
    __shared__ alignas(16) float Sr[128];
    int l = blockIdx.x;
    int t = threadIdx.x;
    if (t < 128) {
        float s = 0.f;
#pragma unroll
        for (int p = 0; p < 8; p++) s += g_scratch_c[((size_t)p * 1024 + l) * 128 + t];
        Sc[t] = s;
    } else {
        int c = t - 128;
        float s = 0.f;
#pragma unroll
        for (int p = 0; p < 16; p++) s += g_scratch_r[((size_t)p * 1024 + l) * 128 + c];
        Sr[c] = s;
    }
    __syncthreads();

    int c = t & 127;
    const float4* wrow = (const float4*)(w2 + (size_t)c * 128);
    const float4* Sv   = (const float4*)((t < 128) ? Sc : Sr);
    float s = 0.f;
#pragma unroll 8
    for (int kk = 0; kk < 32; kk++) {
        float4 wv = wrow[kk], sv = Sv[kk];
        s = fmaf(wv.x, sv.x, s); s = fmaf(wv.y, sv.y, s);
        s = fmaf(wv.z, sv.z, s); s = fmaf(wv.w, sv.w, s);
    }
    float ns = (t < 128) ? g_norm_c[l] : g_norm_r[l];
    float val = (s + ns * b2[c]) / fmaxf(ns, 1.f);
    g_catf[(size_t)l * 1280 + ((t < 128) ? 0 : 128) + c] = val;

    for (int cc = t; cc < 1024; cc += 256)
        g_catf[(size_t)l * 1280 + 256 + cc] = s_s_in[(size_t)l * 1024 + cc];
}

// ---------------- K3: final projection (tf32), swizzled-k staging + wide LDS ----------------
#define PADF 36
__global__ __launch_bounds__(256, 2)
void final_gemm(const float* __restrict__ wc, const float* __restrict__ bc, float* __restrict__ out) {
    __shared__ uint32_t atf[64 * PADF];
    __shared__ uint32_t btf[128 * PADF];
    const int tid = threadIdx.x, w = tid >> 5, lane = tid & 31;
    const int g = lane >> 2, tc = lane & 3;
    const int wr = w & 3, cg = w >> 2;
    const int l0 = blockIdx.y * 64, d0 = blockIdx.x * 128;
    const int q = tid & 7, rload = tid >> 3;      // q: 4-col group, rload: row 0..31

    float d[32];
#pragma unroll
    for (int i = 0; i < 32; i++) d[i] = 0.f;

    float4 va0, va1, vb0, vb1, vb2, vb3;
    auto ldg = [&](int kc) {
        int k0 = kc * 32 + q * 4;
        va0 = *(const float4*)(g_catf + (size_t)(l0 + rload)      * 1280 + k0);
        va1 = *(const float4*)(g_catf + (size_t)(l0 + rload + 32) * 1280 + k0);
        vb0 = *(const float4*)(wc + (size_t)(d0 + rload)      * 1280 + k0);
        vb1 = *(const float4*)(wc + (size_t)(d0 + rload + 32) * 1280 + k0);
        vb2 = *(const float4*)(wc + (size_t)(d0 + rload + 64) * 1280 + k0);
        vb3 = *(const float4*)(wc + (size_t)(d0 + rload + 96) * 1280 + k0);
    };
    // swizzled store: k = q*4 + j  -> sidx = j*8 + q
    auto stv = [&](uint32_t* base, int r, float4 v) {
        uint32_t* p = base + r * PADF + q;
        p[0] = f2tf(v.x); p[8] = f2tf(v.y); p[16] = f2tf(v.z); p[24] = f2tf(v.w);
    };

    ldg(0);
    for (int kc = 0; kc < 40; ++kc) {
        __syncthreads();    // previous compute done
        stv(atf, rload,      va0); stv(atf, rload + 32, va1);
        stv(btf, rload,      vb0); stv(btf, rload + 32, vb1);
        stv(btf, rload + 64, vb2); stv(btf, rload + 96, vb3);
        if (kc + 1 < 40) ldg(kc + 1);
        __syncthreads();    // smem staged

        uint32_t aw0[8], aw1[8];
        *(uint4*)(aw0)     = *(uint4*)&atf[(16 * wr + g)     * PADF + tc * 8];
        *(uint4*)(aw0 + 4) = *(uint4*)&atf[(16 * wr + g)     * PADF + tc * 8 + 4];
        *(uint4*)(aw1)     = *(uint4*)&atf[(16 * wr + 8 + g) * PADF + tc * 8];
        *(uint4*)(aw1 + 4) = *(uint4*)&atf[(16 * wr + 8 + g) * PADF + tc * 8 + 4];
#pragma unroll
        for (int nt = 0; nt < 8; nt++) {
            int row = cg * 64 + nt * 8 + g;
            uint32_t bw[8];
            *(uint4*)(bw)     = *(uint4*)&btf[row * PADF + tc * 8];
            *(uint4*)(bw + 4) = *(uint4*)&btf[row * PADF + tc * 8 + 4];
#pragma unroll
            for (int kp = 0; kp < 4; kp++)
                mma_tf32(d + nt * 4, aw0[2 * kp], aw1[2 * kp], aw0[2 * kp + 1], aw1[2 * kp + 1],
                         bw[2 * kp], bw[2 * kp + 1]);
        }
    }

    int row = l0 + 16 * wr + g;
#pragma unroll
    for (int nt = 0; nt < 8; nt++) {
        int col = d0 + cg * 64 + nt * 8 + tc * 2;
        float bb0 = bc[col], bb1 = bc[col + 1];
        *(float2*)&out[(size_t)row * 1024 + col]       = make_float2(d[nt * 4 + 0] + bb0, d[nt * 4 + 1] + bb1);
        *(float2*)&out[(size_t)(row + 8) * 1024 + col] = make_float2(d[nt * 4 + 2] + bb0, d[nt * 4 + 3] + bb1);
    }
}

// ---------------- launch ----------------
extern "C" void kernel_launch(void* const* d_in, const int* in_sizes, int n_in,
                              void* d_out, int out_size) {
    const float* s_z    = (const float*)d_in[0];
    const float* s_s_in = (const float*)d_in[1];
    const float* mask   = (const float*)d_in[2];
    const float* ln_g   = (const float*)d_in[3];
    const float* ln_b   = (const float*)d_in[4];
    const float* w1     = (const float*)d_in[5];
    const float* b1     = (const float*)d_in[6];
    const float* w2     = (const float*)d_in[7];
    const float* b2     = (const float*)d_in[8];
    const float* wc     = (const float*)d_in[9];
    const float* bc     = (const float*)d_in[10];
    float* out = (float*)d_out;

    cudaFuncSetAttribute(pair_kernel, cudaFuncAttributeMaxDynamicSharedMemorySize, SMEM_PAIR);

    norm_kernel<<<8, 256>>>(mask);
    pair_kernel<<<dim3(8, NLB), 256, SMEM_PAIR>>>(s_z, mask, ln_g, ln_b, w1, b1);
    cat_kernel<<<1024, 256>>>(s_s_in, w2, b2);
    final_gemm<<<dim3(8, 16), 256>>>(wc, bc, out);
}